// round 3
// baseline (speedup 1.0000x reference)
#include <cuda_runtime.h>
#include <cuda_bf16.h>

#define NN 20000
#define EE 640000

// ----------------------------- device scratch -------------------------------
__device__ __align__(16) float g_A[NN * 64];
__device__ __align__(16) float g_B[NN * 64];
__device__ __align__(16) float g_agg[NN * 128];
__device__ int g_deg[NN];
__device__ int g_cursor[NN];
__device__ int g_rowptr[NN + 1];
__device__ int g_csr[EE];
__device__ int g_is64;
__device__ float g_T[81 * 64];   // T[d1][d0][m] = sum_c Wc2[m,c,d1]*Wc1[c,d0]
__device__ float g_Tb[9 * 64];   // Tb[d1][m]   = sum_c Wc2[m,c,d1]*bc1[c]
__device__ float g_G[25 * 49];   // composed 7x7 kernels per (rowcase,colcase)
__device__ float g_Bias[25];     // composed bias per case

__device__ __forceinline__ float* pick(float* p, int id) {
    if (id == 0) return g_A;
    if (id == 1) return g_B;
    if (id == 2) return g_agg;
    return p;
}

// edge fetch helpers (dtype-agnostic)
__device__ __forceinline__ int edge_src(const int* w, int e) {
    if (g_is64) return (int)((const long long*)w)[e];
    return w[e];
}
__device__ __forceinline__ int edge_dst(const int* w, int e) {
    if (g_is64) return (int)((const long long*)w)[EE + e];
    return w[EE + e];
}

// ----------------------------- dtype detect ---------------------------------
__global__ void k_detect(const int* __restrict__ w) {
    if (threadIdx.x == 0 && blockIdx.x == 0) {
        int all0 = 1;
        for (int i = 0; i < 64; i++)
            if (w[2 * i + 1] != 0) { all0 = 0; break; }
        g_is64 = all0;
    }
}

// ----------------------------- CSR build ------------------------------------
__global__ void k_zero() {
    int i = blockIdx.x * 256 + threadIdx.x;
    if (i < NN) { g_deg[i] = 0; g_cursor[i] = 0; }
}

__global__ void k_hist(const int* __restrict__ ei) {
    int e = blockIdx.x * 256 + threadIdx.x;
    if (e < EE) {
        int d = edge_dst(ei, e);
        if ((unsigned)d < NN) atomicAdd(&g_deg[d], 1);
    }
}

__global__ void k_scan() {   // 1 block, 1024 threads
    __shared__ int ws[32];
    __shared__ int base_s;
    int tid = threadIdx.x, lane = tid & 31, wid = tid >> 5;
    if (tid == 0) { g_rowptr[0] = 0; base_s = 0; }
    __syncthreads();
    for (int start = 0; start < NN; start += 1024) {
        int i = start + tid;
        int v = (i < NN) ? g_deg[i] : 0;
        int x = v;
        #pragma unroll
        for (int off = 1; off < 32; off <<= 1) {
            int n = __shfl_up_sync(0xffffffffu, x, off);
            if (lane >= off) x += n;
        }
        if (lane == 31) ws[wid] = x;
        __syncthreads();
        if (wid == 0) {
            int w = ws[lane];
            #pragma unroll
            for (int off = 1; off < 32; off <<= 1) {
                int n = __shfl_up_sync(0xffffffffu, w, off);
                if (lane >= off) w += n;
            }
            ws[lane] = w;
        }
        __syncthreads();
        int incl = x + (wid ? ws[wid - 1] : 0) + base_s;
        if (i < NN) g_rowptr[i + 1] = incl;
        __syncthreads();
        if (tid == 1023) base_s = incl;
        __syncthreads();
    }
}

__global__ void k_scatter(const int* __restrict__ ei) {
    int e = blockIdx.x * 256 + threadIdx.x;
    if (e < EE) {
        int s = edge_src(ei, e);
        int d = edge_dst(ei, e);
        if ((unsigned)s < NN && (unsigned)d < NN) {
            int pos = atomicAdd(&g_cursor[d], 1);
            int idx = g_rowptr[d] + pos;
            if ((unsigned)idx < EE) g_csr[idx] = s;
        }
    }
}

// ----------------------------- mean aggregation ------------------------------
// warp per node; D = 64 or 128 features (float2 per lane per 64-chunk)
template <int D>
__global__ void k_agg(const float* __restrict__ xp, int xid) {
    const float* x = pick((float*)xp, xid);
    int node = blockIdx.x * 8 + (threadIdx.x >> 5);
    int lane = threadIdx.x & 31;
    if (node >= NN) return;
    int a = g_rowptr[node], b = g_rowptr[node + 1];
    const float2* xv = (const float2*)x;
    const int Q = D / 64;
    float2 acc0[Q], acc1[Q];
    #pragma unroll
    for (int q = 0; q < Q; q++) {
        acc0[q] = make_float2(0.f, 0.f);
        acc1[q] = make_float2(0.f, 0.f);
    }
    int t = a;
    for (; t + 1 < b; t += 2) {
        int s0 = g_csr[t], s1 = g_csr[t + 1];
        #pragma unroll
        for (int q = 0; q < Q; q++) {
            float2 v0 = __ldg(&xv[(size_t)s0 * (D / 2) + q * 32 + lane]);
            float2 v1 = __ldg(&xv[(size_t)s1 * (D / 2) + q * 32 + lane]);
            acc0[q].x += v0.x; acc0[q].y += v0.y;
            acc1[q].x += v1.x; acc1[q].y += v1.y;
        }
    }
    if (t < b) {
        int s0 = g_csr[t];
        #pragma unroll
        for (int q = 0; q < Q; q++) {
            float2 v0 = __ldg(&xv[(size_t)s0 * (D / 2) + q * 32 + lane]);
            acc0[q].x += v0.x; acc0[q].y += v0.y;
        }
    }
    int deg = b - a;
    float inv = 1.0f / (float)(deg > 0 ? deg : 1);
    float2* ag = (float2*)g_agg;
    #pragma unroll
    for (int q = 0; q < Q; q++) {
        ag[(size_t)node * (D / 2) + q * 32 + lane] =
            make_float2((acc0[q].x + acc1[q].x) * inv, (acc0[q].y + acc1[q].y) * inv);
    }
}

// ----------------------------- SAGE linear -----------------------------------
// out[n,o] = sum_k agg[n,k]*Wl[o,k] + xin[n,k]*Wr[o,k] + bl[o]
template <int DIN, int DOUT>
__global__ void k_lin(const float* __restrict__ xinp, int xid,
                      const float* __restrict__ Wl, const float* __restrict__ bl,
                      const float* __restrict__ Wr,
                      float* __restrict__ outp, int oid) {
    const float* xin = pick((float*)xinp, xid);
    float* out = pick(outp, oid);
    const float* agg = g_agg;
    const int RPT = 32 * DOUT / 256;   // rows per thread
    __shared__ float sWl[32 * (DOUT + 1)];
    __shared__ float sWr[32 * (DOUT + 1)];
    __shared__ float sA[32 * 33];
    __shared__ float sX[32 * 33];
    int tid = threadIdx.x;
    int o = tid % DOUT, rg = tid / DOUT;
    int n0 = blockIdx.x * 32;
    float acc[RPT];
    #pragma unroll
    for (int r = 0; r < RPT; r++) acc[r] = 0.f;

    for (int kt = 0; kt < DIN; kt += 32) {
        for (int id = tid; id < 32 * DOUT; id += 256) {
            int kk = id & 31, oo = id >> 5;
            sWl[kk * (DOUT + 1) + oo] = Wl[oo * DIN + kt + kk];
            sWr[kk * (DOUT + 1) + oo] = Wr[oo * DIN + kt + kk];
        }
        for (int id = tid; id < 32 * 32; id += 256) {
            int kk = id & 31, r = id >> 5;
            sA[kk * 33 + r] = agg[(size_t)(n0 + r) * DIN + kt + kk];
            sX[kk * 33 + r] = xin[(size_t)(n0 + r) * DIN + kt + kk];
        }
        __syncthreads();
        #pragma unroll
        for (int k = 0; k < 32; k++) {
            float wl = sWl[k * (DOUT + 1) + o];
            float wr = sWr[k * (DOUT + 1) + o];
            #pragma unroll
            for (int r = 0; r < RPT; r++) {
                acc[r] += sA[k * 33 + rg * RPT + r] * wl;
                acc[r] += sX[k * 33 + rg * RPT + r] * wr;
            }
        }
        __syncthreads();
    }
    float b = __ldg(&bl[o]);
    #pragma unroll
    for (int r = 0; r < RPT; r++)
        out[(size_t)(n0 + rg * RPT + r) * DOUT + o] = acc[r] + b;
}

// ----------------------------- conv composition precompute -------------------
__global__ void k_T(const float* __restrict__ Wc1, const float* __restrict__ Wc2,
                    const float* __restrict__ bc1) {
    int m = threadIdx.x;               // 64
    int d1 = blockIdx.x / 9, d0 = blockIdx.x % 9;   // 81 blocks
    float s = 0.f;
    for (int c = 0; c < 64; c++)
        s += Wc2[(m * 64 + c) * 9 + d1] * Wc1[c * 9 + d0];
    g_T[(d1 * 9 + d0) * 64 + m] = s;
    if (d0 == 0) {
        float sb = 0.f;
        for (int c = 0; c < 64; c++)
            sb += Wc2[(m * 64 + c) * 9 + d1] * bc1[c];
        g_Tb[d1 * 64 + m] = sb;
    }
}

__device__ __forceinline__ bool m1(int rc, int d) {   // level-1 pos inside
    if (rc == 0) return d >= 0;
    if (rc == 4) return d <= 0;
    return true;
}
__device__ __forceinline__ bool m2(int rc, int s) {   // level-2 pos inside
    if (rc == 0) return s >= 0;
    if (rc == 1) return s >= -1;
    if (rc == 3) return s <= 1;
    if (rc == 4) return s <= 0;
    return true;
}

__global__ void k_G(const float* __restrict__ Wc3, const float* __restrict__ bc2,
                    const float* __restrict__ bc3) {
    int cs = blockIdx.x;               // 25 cases
    int rc = cs / 5, cc = cs % 5;
    int t = threadIdx.x;               // 64 threads
    if (t < 49) {
        int Dr = t / 7 - 3, Dc = t % 7 - 3;
        float acc = 0.f;
        for (int d2 = 0; d2 < 9; d2++) {
            int d2r = d2 / 3 - 1, d2c = d2 % 3 - 1;
            if (!m1(rc, d2r) || !m1(cc, d2c)) continue;
            for (int d1 = 0; d1 < 9; d1++) {
                int d1r = d1 / 3 - 1, d1c = d1 % 3 - 1;
                if (!m2(rc, d2r + d1r) || !m2(cc, d2c + d1c)) continue;
                int d0r = Dr - d2r - d1r, d0c = Dc - d2c - d1c;
                if (d0r < -1 || d0r > 1 || d0c < -1 || d0c > 1) continue;
                int d0 = (d0r + 1) * 3 + (d0c + 1);
                float s = 0.f;
                for (int m = 0; m < 64; m++)
                    s += Wc3[m * 9 + d2] * g_T[(d1 * 9 + d0) * 64 + m];
                acc += s;
            }
        }
        g_G[cs * 49 + t] = acc;
    }
    if (t == 49) {
        float acc = __ldg(&bc3[0]);
        for (int d2 = 0; d2 < 9; d2++) {
            int d2r = d2 / 3 - 1, d2c = d2 % 3 - 1;
            if (!m1(rc, d2r) || !m1(cc, d2c)) continue;
            for (int m = 0; m < 64; m++) acc += Wc3[m * 9 + d2] * bc2[m];
            for (int d1 = 0; d1 < 9; d1++) {
                int d1r = d1 / 3 - 1, d1c = d1 % 3 - 1;
                if (!m2(rc, d2r + d1r) || !m2(cc, d2c + d1c)) continue;
                for (int m = 0; m < 64; m++) acc += Wc3[m * 9 + d2] * g_Tb[d1 * 64 + m];
            }
        }
        g_Bias[cs] = acc;
    }
}

// ---------------- fused (composed-conv + residual + W2 linear) ---------------
// reads g_A (h3), writes g_B = (convstack(h3) + h3) @ W2.T + b2
__global__ void k_conv(const float* __restrict__ W2, const float* __restrict__ b2) {
    __shared__ float sH[38][64];
    __shared__ float sG[25][49];
    __shared__ float sBias[25];
    __shared__ float sPre[64][33];   // [k(col)][row]
    __shared__ float sW[32][65];
    const float* h = g_A;
    float* out = g_B;
    int tid = threadIdx.x;
    int n0 = blockIdx.x * 32;

    for (int id = tid; id < 38 * 64; id += 256) {
        int r = id >> 6, c = id & 63;
        int gr = n0 - 3 + r;
        sH[r][c] = (gr >= 0 && gr < NN) ? h[(size_t)gr * 64 + c] : 0.f;
    }
    for (int id = tid; id < 25 * 49; id += 256) sG[id / 49][id % 49] = g_G[id];
    if (tid < 25) sBias[tid] = g_Bias[tid];
    __syncthreads();

    for (int id = tid; id < 32 * 64; id += 256) {
        int r = id >> 6, c = id & 63;
        int gi = n0 + r;
        int rc = (gi == 0) ? 0 : (gi == 1) ? 1 : (gi == NN - 2) ? 3 : (gi == NN - 1) ? 4 : 2;
        int cc = (c == 0) ? 0 : (c == 1) ? 1 : (c == 62) ? 3 : (c == 63) ? 4 : 2;
        const float* g = sG[rc * 5 + cc];
        float acc = sBias[rc * 5 + cc];
        #pragma unroll
        for (int dr = 0; dr < 7; dr++) {
            #pragma unroll
            for (int dc = 0; dc < 7; dc++) {
                int cj = c + dc - 3;
                if (cj >= 0 && cj < 64)
                    acc += g[dr * 7 + dc] * sH[r + dr][cj];
            }
        }
        acc += sH[r + 3][c];        // residual out_1
        sPre[c][r] = acc;
    }
    __syncthreads();

    int o = tid % 64, rg = tid / 64;
    float acc[8];
    #pragma unroll
    for (int r = 0; r < 8; r++) acc[r] = 0.f;
    for (int kt = 0; kt < 64; kt += 32) {
        for (int id = tid; id < 32 * 64; id += 256) {
            int kk = id & 31, oo = id >> 5;
            sW[kk][oo] = W2[oo * 64 + kt + kk];
        }
        __syncthreads();
        #pragma unroll
        for (int k = 0; k < 32; k++) {
            float w = sW[k][o];
            #pragma unroll
            for (int r = 0; r < 8; r++)
                acc[r] += sPre[kt + k][rg * 8 + r] * w;
        }
        __syncthreads();
    }
    float bb = __ldg(&b2[o]);
    #pragma unroll
    for (int r = 0; r < 8; r++)
        out[(size_t)(n0 + rg * 8 + r) * 64 + o] = acc[r] + bb;
}

// ----------------------------- launch ----------------------------------------
extern "C" void kernel_launch(void* const* d_in, const int* in_sizes, int n_in,
                              void* d_out, int out_size) {
    const float* x     = (const float*)d_in[0];
    const int*   ei    = (const int*)d_in[1];      // int32 or int64 (auto-detected)
    const float* Wl1 = (const float*)d_in[2];
    const float* bl1 = (const float*)d_in[3];
    const float* Wr1 = (const float*)d_in[4];
    const float* Wl2 = (const float*)d_in[5];
    const float* bl2 = (const float*)d_in[6];
    const float* Wr2 = (const float*)d_in[7];
    const float* Wl3 = (const float*)d_in[8];
    const float* bl3 = (const float*)d_in[9];
    const float* Wr3 = (const float*)d_in[10];
    const float* Wc1 = (const float*)d_in[11];
    const float* bc1 = (const float*)d_in[12];
    const float* Wc2 = (const float*)d_in[13];
    const float* bc2 = (const float*)d_in[14];
    const float* Wc3 = (const float*)d_in[15];
    const float* bc3 = (const float*)d_in[16];
    const float* W2  = (const float*)d_in[17];
    const float* b2  = (const float*)d_in[18];
    float* out = (float*)d_out;

    // dtype detect + CSR build
    k_detect<<<1, 32>>>(ei);
    k_zero<<<(NN + 255) / 256, 256>>>();
    k_hist<<<(EE + 255) / 256, 256>>>(ei);
    k_scan<<<1, 1024>>>();
    k_scatter<<<(EE + 255) / 256, 256>>>(ei);

    // conv composition precompute
    k_T<<<81, 64>>>(Wc1, Wc2, bc1);
    k_G<<<25, 64>>>(Wc3, bc2, bc3);

    // sage1: x(128) -> g_A
    k_agg<128><<<2500, 256>>>(x, -1);
    k_lin<128, 64><<<625, 256>>>(x, -1, Wl1, bl1, Wr1, nullptr, 0);
    // sage2: g_A -> g_B
    k_agg<64><<<2500, 256>>>(nullptr, 0);
    k_lin<64, 64><<<625, 256>>>(nullptr, 0, Wl2, bl2, Wr2, nullptr, 1);
    // sage2 again: g_B -> g_A  (= out_1)
    k_agg<64><<<2500, 256>>>(nullptr, 1);
    k_lin<64, 64><<<625, 256>>>(nullptr, 1, Wl2, bl2, Wr2, nullptr, 0);

    // composed conv + residual + W2 linear: g_A -> g_B
    k_conv<<<625, 256>>>(W2, b2);

    // sage2: g_B -> g_A
    k_agg<64><<<2500, 256>>>(nullptr, 1);
    k_lin<64, 64><<<625, 256>>>(nullptr, 1, Wl2, bl2, Wr2, nullptr, 0);
    // sage2: g_A -> g_B
    k_agg<64><<<2500, 256>>>(nullptr, 0);
    k_lin<64, 64><<<625, 256>>>(nullptr, 0, Wl2, bl2, Wr2, nullptr, 1);
    // sage3: g_B -> d_out (64 -> 32)
    k_agg<64><<<2500, 256>>>(nullptr, 1);
    k_lin<64, 32><<<625, 256>>>(nullptr, 1, Wl3, bl3, Wr3, out, -1);
}

// round 4
// speedup vs baseline: 1.1120x; 1.1120x over previous
#include <cuda_runtime.h>
#include <cuda_bf16.h>

#define NN 20000
#define EE 640000

// ----------------------------- device scratch -------------------------------
__device__ __align__(16) float g_A[NN * 64];   // h buffer
__device__ __align__(16) float g_B[NN * 64];   // conv-block output buffer
__device__ __align__(16) float g_U[NN * 64];   // pre-transformed neighbor term
__device__ __align__(16) float g_V[NN * 64];   // pre-transformed root term (+bias)
__device__ int g_deg[NN];
__device__ int g_cursor[NN];
__device__ int g_rowptr[NN + 1];
__device__ int g_csr[EE];
__device__ int g_bsum[32];
__device__ int g_is64;
__device__ float g_T[81 * 64];
__device__ float g_Tb[9 * 64];
__device__ float g_G[25 * 49];
__device__ float g_Bias[25];

// edge fetch helpers (dtype-agnostic: int32 or int64 edge_index)
__device__ __forceinline__ int edge_src(const int* w, int e) {
    if (g_is64) return (int)((const long long*)w)[e];
    return w[e];
}
__device__ __forceinline__ int edge_dst(const int* w, int e) {
    if (g_is64) return (int)((const long long*)w)[EE + e];
    return w[EE + e];
}

// ----------------------------- init + dtype detect ---------------------------
__global__ void k_zero(const int* __restrict__ w) {
    int i = blockIdx.x * 256 + threadIdx.x;
    if (i < NN) { g_deg[i] = 0; g_cursor[i] = 0; }
    if (i == 0) {
        int all0 = 1;
        for (int j = 0; j < 64; j++)
            if (w[2 * j + 1] != 0) { all0 = 0; break; }
        g_is64 = all0;
    }
}

// ----------------------------- CSR build ------------------------------------
__global__ void k_hist(const int* __restrict__ ei) {
    int e = blockIdx.x * 256 + threadIdx.x;
    if (e < EE) {
        int d = edge_dst(ei, e);
        if ((unsigned)d < NN) atomicAdd(&g_deg[d], 1);
    }
}

// hierarchical scan: A (per-1024-block inclusive) -> B (scan 20 sums) -> C (add)
__global__ void k_scanA() {
    __shared__ int ws[32];
    int tid = threadIdx.x, lane = tid & 31, wid = tid >> 5;
    int i = blockIdx.x * 1024 + tid;
    int v = (i < NN) ? g_deg[i] : 0;
    int x = v;
    #pragma unroll
    for (int off = 1; off < 32; off <<= 1) {
        int n = __shfl_up_sync(0xffffffffu, x, off);
        if (lane >= off) x += n;
    }
    if (lane == 31) ws[wid] = x;
    __syncthreads();
    if (wid == 0) {
        int w = ws[lane];
        #pragma unroll
        for (int off = 1; off < 32; off <<= 1) {
            int n = __shfl_up_sync(0xffffffffu, w, off);
            if (lane >= off) w += n;
        }
        ws[lane] = w;
    }
    __syncthreads();
    int incl = x + (wid ? ws[wid - 1] : 0);
    if (i < NN) g_rowptr[i + 1] = incl;
    if (tid == 1023) g_bsum[blockIdx.x] = incl;
}

__global__ void k_scanB() {   // 1 block, 32 threads
    int tid = threadIdx.x;
    int v = (tid < 20) ? g_bsum[tid] : 0;
    int x = v;
    #pragma unroll
    for (int off = 1; off < 32; off <<= 1) {
        int n = __shfl_up_sync(0xffffffffu, x, off);
        if (tid >= off) x += n;
    }
    if (tid < 20) g_bsum[tid] = x - v;   // exclusive
}

__global__ void k_scanC() {
    int i = blockIdx.x * 1024 + threadIdx.x;
    if (i < NN) g_rowptr[i + 1] += g_bsum[blockIdx.x];
    if (i == 0) g_rowptr[0] = 0;
}

__global__ void k_scatter(const int* __restrict__ ei) {
    int e = blockIdx.x * 256 + threadIdx.x;
    if (e < EE) {
        int s = edge_src(ei, e);
        int d = edge_dst(ei, e);
        if ((unsigned)s < NN && (unsigned)d < NN) {
            int pos = atomicAdd(&g_cursor[d], 1);
            int idx = g_rowptr[d] + pos;
            if ((unsigned)idx < EE) g_csr[idx] = s;
        }
    }
}

// ----------------------------- pre-transform GEMM ----------------------------
// U[n,o] = sum_k xin[n,k]*Wl[o,k];  V[n,o] = sum_k xin[n,k]*Wr[o,k] + bl[o]
template <int DIN, int DOUT>
__global__ void k_pre(const float* __restrict__ xin,
                      const float* __restrict__ Wl, const float* __restrict__ Wr,
                      const float* __restrict__ bl,
                      float* __restrict__ U, float* __restrict__ Vout) {
    const int RPT = 32 * DOUT / 256;
    __shared__ float sWl[32 * (DOUT + 1)];
    __shared__ float sWr[32 * (DOUT + 1)];
    __shared__ float sX[32 * 33];
    int tid = threadIdx.x;
    int o = tid % DOUT, rg = tid / DOUT;
    int n0 = blockIdx.x * 32;
    float accU[RPT], accV[RPT];
    #pragma unroll
    for (int r = 0; r < RPT; r++) { accU[r] = 0.f; accV[r] = 0.f; }

    for (int kt = 0; kt < DIN; kt += 32) {
        for (int id = tid; id < 32 * DOUT; id += 256) {
            int kk = id & 31, oo = id >> 5;
            sWl[kk * (DOUT + 1) + oo] = Wl[oo * DIN + kt + kk];
            sWr[kk * (DOUT + 1) + oo] = Wr[oo * DIN + kt + kk];
        }
        for (int id = tid; id < 32 * 32; id += 256) {
            int kk = id & 31, r = id >> 5;
            sX[kk * 33 + r] = xin[(size_t)(n0 + r) * DIN + kt + kk];
        }
        __syncthreads();
        #pragma unroll
        for (int k = 0; k < 32; k++) {
            float wl = sWl[k * (DOUT + 1) + o];
            float wr = sWr[k * (DOUT + 1) + o];
            #pragma unroll
            for (int r = 0; r < RPT; r++) {
                float xv = sX[k * 33 + rg * RPT + r];
                accU[r] += xv * wl;
                accV[r] += xv * wr;
            }
        }
        __syncthreads();
    }
    float b = __ldg(&bl[o]);
    #pragma unroll
    for (int r = 0; r < RPT; r++) {
        size_t row = (size_t)(n0 + rg * RPT + r);
        U[row * DOUT + o] = accU[r];
        Vout[row * DOUT + o] = accV[r] + b;
    }
}

// ----------------------------- mean-agg + add root term ----------------------
// out[n,:] = mean_{s in N(n)} U[s,:] + V[n,:]
template <int D>
__global__ void k_aggadd(const float* __restrict__ U, const float* __restrict__ V,
                         float* __restrict__ out) {
    int node = blockIdx.x * 8 + (threadIdx.x >> 5);
    int lane = threadIdx.x & 31;
    if (node >= NN) return;
    int a = g_rowptr[node], b = g_rowptr[node + 1];
    int deg = b - a;
    float inv = 1.0f / (float)(deg > 0 ? deg : 1);

    if (D == 64) {
        const float2* Uv = (const float2*)U;
        float2 a0 = make_float2(0.f, 0.f), a1 = a0, a2 = a0, a3 = a0;
        int t = a;
        for (; t + 3 < b; t += 4) {
            int s0 = g_csr[t], s1 = g_csr[t + 1], s2 = g_csr[t + 2], s3 = g_csr[t + 3];
            float2 v0 = __ldg(&Uv[(size_t)s0 * 32 + lane]);
            float2 v1 = __ldg(&Uv[(size_t)s1 * 32 + lane]);
            float2 v2 = __ldg(&Uv[(size_t)s2 * 32 + lane]);
            float2 v3 = __ldg(&Uv[(size_t)s3 * 32 + lane]);
            a0.x += v0.x; a0.y += v0.y;
            a1.x += v1.x; a1.y += v1.y;
            a2.x += v2.x; a2.y += v2.y;
            a3.x += v3.x; a3.y += v3.y;
        }
        for (; t < b; t++) {
            int s0 = g_csr[t];
            float2 v0 = __ldg(&Uv[(size_t)s0 * 32 + lane]);
            a0.x += v0.x; a0.y += v0.y;
        }
        float2 vv = __ldg(&((const float2*)V)[(size_t)node * 32 + lane]);
        float2 res;
        res.x = (a0.x + a1.x + a2.x + a3.x) * inv + vv.x;
        res.y = (a0.y + a1.y + a2.y + a3.y) * inv + vv.y;
        ((float2*)out)[(size_t)node * 32 + lane] = res;
    } else {   // D == 32
        float a0 = 0.f, a1 = 0.f, a2 = 0.f, a3 = 0.f;
        int t = a;
        for (; t + 3 < b; t += 4) {
            int s0 = g_csr[t], s1 = g_csr[t + 1], s2 = g_csr[t + 2], s3 = g_csr[t + 3];
            a0 += __ldg(&U[(size_t)s0 * 32 + lane]);
            a1 += __ldg(&U[(size_t)s1 * 32 + lane]);
            a2 += __ldg(&U[(size_t)s2 * 32 + lane]);
            a3 += __ldg(&U[(size_t)s3 * 32 + lane]);
        }
        for (; t < b; t++) a0 += __ldg(&U[(size_t)g_csr[t] * 32 + lane]);
        float vv = __ldg(&V[(size_t)node * 32 + lane]);
        out[(size_t)node * 32 + lane] = (a0 + a1 + a2 + a3) * inv + vv;
    }
}

// ----------------------------- conv composition precompute -------------------
__global__ void k_T(const float* __restrict__ Wc1, const float* __restrict__ Wc2,
                    const float* __restrict__ bc1) {
    int m = threadIdx.x;
    int d1 = blockIdx.x / 9, d0 = blockIdx.x % 9;
    float s = 0.f;
    for (int c = 0; c < 64; c++)
        s += Wc2[(m * 64 + c) * 9 + d1] * Wc1[c * 9 + d0];
    g_T[(d1 * 9 + d0) * 64 + m] = s;
    if (d0 == 0) {
        float sb = 0.f;
        for (int c = 0; c < 64; c++)
            sb += Wc2[(m * 64 + c) * 9 + d1] * bc1[c];
        g_Tb[d1 * 64 + m] = sb;
    }
}

__device__ __forceinline__ bool m1(int rc, int d) {
    if (rc == 0) return d >= 0;
    if (rc == 4) return d <= 0;
    return true;
}
__device__ __forceinline__ bool m2(int rc, int s) {
    if (rc == 0) return s >= 0;
    if (rc == 1) return s >= -1;
    if (rc == 3) return s <= 1;
    if (rc == 4) return s <= 0;
    return true;
}

__global__ void k_G(const float* __restrict__ Wc3, const float* __restrict__ bc2,
                    const float* __restrict__ bc3) {
    int cs = blockIdx.x;
    int rc = cs / 5, cc = cs % 5;
    int t = threadIdx.x;
    if (t < 49) {
        int Dr = t / 7 - 3, Dc = t % 7 - 3;
        float acc = 0.f;
        for (int d2 = 0; d2 < 9; d2++) {
            int d2r = d2 / 3 - 1, d2c = d2 % 3 - 1;
            if (!m1(rc, d2r) || !m1(cc, d2c)) continue;
            for (int d1 = 0; d1 < 9; d1++) {
                int d1r = d1 / 3 - 1, d1c = d1 % 3 - 1;
                if (!m2(rc, d2r + d1r) || !m2(cc, d2c + d1c)) continue;
                int d0r = Dr - d2r - d1r, d0c = Dc - d2c - d1c;
                if (d0r < -1 || d0r > 1 || d0c < -1 || d0c > 1) continue;
                int d0 = (d0r + 1) * 3 + (d0c + 1);
                float s = 0.f;
                for (int m = 0; m < 64; m++)
                    s += Wc3[m * 9 + d2] * g_T[(d1 * 9 + d0) * 64 + m];
                acc += s;
            }
        }
        g_G[cs * 49 + t] = acc;
    }
    if (t == 49) {
        float acc = __ldg(&bc3[0]);
        for (int d2 = 0; d2 < 9; d2++) {
            int d2r = d2 / 3 - 1, d2c = d2 % 3 - 1;
            if (!m1(rc, d2r) || !m1(cc, d2c)) continue;
            for (int m = 0; m < 64; m++) acc += Wc3[m * 9 + d2] * bc2[m];
            for (int d1 = 0; d1 < 9; d1++) {
                int d1r = d1 / 3 - 1, d1c = d1 % 3 - 1;
                if (!m2(rc, d2r + d1r) || !m2(cc, d2c + d1c)) continue;
                for (int m = 0; m < 64; m++) acc += Wc3[m * 9 + d2] * g_Tb[d1 * 64 + m];
            }
        }
        g_Bias[cs] = acc;
    }
}

// ---------------- fused (composed-conv + residual + W2 linear) ---------------
__global__ void k_conv(const float* __restrict__ W2, const float* __restrict__ b2) {
    __shared__ float sH[38][64];
    __shared__ float sG[25][49];
    __shared__ float sBias[25];
    __shared__ float sPre[64][33];
    __shared__ float sW[32][65];
    const float* h = g_A;
    float* out = g_B;
    int tid = threadIdx.x;
    int n0 = blockIdx.x * 32;

    for (int id = tid; id < 38 * 64; id += 256) {
        int r = id >> 6, c = id & 63;
        int gr = n0 - 3 + r;
        sH[r][c] = (gr >= 0 && gr < NN) ? h[(size_t)gr * 64 + c] : 0.f;
    }
    for (int id = tid; id < 25 * 49; id += 256) sG[id / 49][id % 49] = g_G[id];
    if (tid < 25) sBias[tid] = g_Bias[tid];
    __syncthreads();

    for (int id = tid; id < 32 * 64; id += 256) {
        int r = id >> 6, c = id & 63;
        int gi = n0 + r;
        int rc = (gi == 0) ? 0 : (gi == 1) ? 1 : (gi == NN - 2) ? 3 : (gi == NN - 1) ? 4 : 2;
        int cc = (c == 0) ? 0 : (c == 1) ? 1 : (c == 62) ? 3 : (c == 63) ? 4 : 2;
        const float* g = sG[rc * 5 + cc];
        float acc = sBias[rc * 5 + cc];
        #pragma unroll
        for (int dr = 0; dr < 7; dr++) {
            #pragma unroll
            for (int dc = 0; dc < 7; dc++) {
                int cj = c + dc - 3;
                if (cj >= 0 && cj < 64)
                    acc += g[dr * 7 + dc] * sH[r + dr][cj];
            }
        }
        acc += sH[r + 3][c];
        sPre[c][r] = acc;
    }
    __syncthreads();

    int o = tid % 64, rg = tid / 64;
    float acc[8];
    #pragma unroll
    for (int r = 0; r < 8; r++) acc[r] = 0.f;
    for (int kt = 0; kt < 64; kt += 32) {
        for (int id = tid; id < 32 * 64; id += 256) {
            int kk = id & 31, oo = id >> 5;
            sW[kk][oo] = W2[oo * 64 + kt + kk];
        }
        __syncthreads();
        #pragma unroll
        for (int k = 0; k < 32; k++) {
            float w = sW[k][o];
            #pragma unroll
            for (int r = 0; r < 8; r++)
                acc[r] += sPre[kt + k][rg * 8 + r] * w;
        }
        __syncthreads();
    }
    float bb = __ldg(&b2[o]);
    #pragma unroll
    for (int r = 0; r < 8; r++)
        out[(size_t)(n0 + rg * 8 + r) * 64 + o] = acc[r] + bb;
}

// ----------------------------- launch ----------------------------------------
extern "C" void kernel_launch(void* const* d_in, const int* in_sizes, int n_in,
                              void* d_out, int out_size) {
    const float* x   = (const float*)d_in[0];
    const int*   ei  = (const int*)d_in[1];
    const float* Wl1 = (const float*)d_in[2];
    const float* bl1 = (const float*)d_in[3];
    const float* Wr1 = (const float*)d_in[4];
    const float* Wl2 = (const float*)d_in[5];
    const float* bl2 = (const float*)d_in[6];
    const float* Wr2 = (const float*)d_in[7];
    const float* Wl3 = (const float*)d_in[8];
    const float* bl3 = (const float*)d_in[9];
    const float* Wr3 = (const float*)d_in[10];
    const float* Wc1 = (const float*)d_in[11];
    const float* bc1 = (const float*)d_in[12];
    const float* Wc2 = (const float*)d_in[13];
    const float* bc2 = (const float*)d_in[14];
    const float* Wc3 = (const float*)d_in[15];
    const float* bc3 = (const float*)d_in[16];
    const float* W2  = (const float*)d_in[17];
    const float* b2  = (const float*)d_in[18];
    float* out = (float*)d_out;

    float *pA, *pB, *pU, *pV;
    cudaGetSymbolAddress((void**)&pA, g_A);
    cudaGetSymbolAddress((void**)&pB, g_B);
    cudaGetSymbolAddress((void**)&pU, g_U);
    cudaGetSymbolAddress((void**)&pV, g_V);

    // init + CSR build
    k_zero<<<(NN + 255) / 256, 256>>>(ei);
    k_hist<<<(EE + 255) / 256, 256>>>(ei);
    k_scanA<<<20, 1024>>>();
    k_scanB<<<1, 32>>>();
    k_scanC<<<20, 1024>>>();
    k_scatter<<<(EE + 255) / 256, 256>>>(ei);

    // conv composition precompute
    k_T<<<81, 64>>>(Wc1, Wc2, bc1);
    k_G<<<25, 64>>>(Wc3, bc2, bc3);

    // sage1: x -> h1 (g_A)
    k_pre<128, 64><<<625, 256>>>(x, Wl1, Wr1, bl1, pU, pV);
    k_aggadd<64><<<2500, 256>>>(pU, pV, pA);
    // sage2: h1 -> h2 (g_A)
    k_pre<64, 64><<<625, 256>>>(pA, Wl2, Wr2, bl2, pU, pV);
    k_aggadd<64><<<2500, 256>>>(pU, pV, pA);
    // sage2 again: h2 -> h3 (g_A)  (= out_1)
    k_pre<64, 64><<<625, 256>>>(pA, Wl2, Wr2, bl2, pU, pV);
    k_aggadd<64><<<2500, 256>>>(pU, pV, pA);

    // composed conv + residual + W2 linear: g_A -> g_B
    k_conv<<<625, 256>>>(W2, b2);

    // sage2: g_B -> g_A
    k_pre<64, 64><<<625, 256>>>(pB, Wl2, Wr2, bl2, pU, pV);
    k_aggadd<64><<<2500, 256>>>(pU, pV, pA);
    // sage2: g_A -> g_B
    k_pre<64, 64><<<625, 256>>>(pA, Wl2, Wr2, bl2, pU, pV);
    k_aggadd<64><<<2500, 256>>>(pU, pV, pB);
    // sage3: g_B -> out (64 -> 32; agg on 32-dim U)
    k_pre<64, 32><<<625, 256>>>(pB, Wl3, Wr3, bl3, pU, pV);
    k_aggadd<32><<<2500, 256>>>(pU, pV, out);
}

// round 5
// speedup vs baseline: 1.1447x; 1.0294x over previous
#include <cuda_runtime.h>
#include <cuda_bf16.h>

#define NN 20000
#define EE 640000

// ----------------------------- device scratch -------------------------------
__device__ __align__(16) float g_A[NN * 64];   // h buffer
__device__ __align__(16) float g_B[NN * 64];   // conv-block output buffer
__device__ __align__(16) float g_U[NN * 64];   // pre-transformed neighbor term
__device__ __align__(16) float g_V[NN * 64];   // pre-transformed root term (+bias)
__device__ int g_deg[NN];
__device__ int g_cursor[NN];
__device__ int g_rowptr[NN + 1];
__device__ int g_csr[EE];
__device__ int g_bsum[32];
__device__ int g_is64;
__device__ float g_T[81 * 64];
__device__ float g_Tb[9 * 64];
__device__ float g_G[25 * 49];
__device__ float g_Bias[25];

// edge fetch helpers (dtype-agnostic: int32 or int64 edge_index)
__device__ __forceinline__ int edge_src(const int* w, int e) {
    if (g_is64) return (int)((const long long*)w)[e];
    return w[e];
}
__device__ __forceinline__ int edge_dst(const int* w, int e) {
    if (g_is64) return (int)((const long long*)w)[EE + e];
    return w[EE + e];
}

// ----------------------------- init + dtype detect ---------------------------
__global__ void k_zero(const int* __restrict__ w) {
    int i = blockIdx.x * 256 + threadIdx.x;
    if (i < NN) { g_deg[i] = 0; g_cursor[i] = 0; }
    if (i == 0) {
        int all0 = 1;
        for (int j = 0; j < 64; j++)
            if (w[2 * j + 1] != 0) { all0 = 0; break; }
        g_is64 = all0;
    }
}

// ----------------------------- CSR build ------------------------------------
__global__ void k_hist(const int* __restrict__ ei) {
    int e = blockIdx.x * 256 + threadIdx.x;
    if (e < EE) {
        int d = edge_dst(ei, e);
        if ((unsigned)d < NN) atomicAdd(&g_deg[d], 1);
    }
}

__global__ void k_scanA() {
    __shared__ int ws[32];
    int tid = threadIdx.x, lane = tid & 31, wid = tid >> 5;
    int i = blockIdx.x * 1024 + tid;
    int v = (i < NN) ? g_deg[i] : 0;
    int x = v;
    #pragma unroll
    for (int off = 1; off < 32; off <<= 1) {
        int n = __shfl_up_sync(0xffffffffu, x, off);
        if (lane >= off) x += n;
    }
    if (lane == 31) ws[wid] = x;
    __syncthreads();
    if (wid == 0) {
        int w = ws[lane];
        #pragma unroll
        for (int off = 1; off < 32; off <<= 1) {
            int n = __shfl_up_sync(0xffffffffu, w, off);
            if (lane >= off) w += n;
        }
        ws[lane] = w;
    }
    __syncthreads();
    int incl = x + (wid ? ws[wid - 1] : 0);
    if (i < NN) g_rowptr[i + 1] = incl;
    if (tid == 1023) g_bsum[blockIdx.x] = incl;
}

// fused: per-block redundant scan of the 20 partial sums, then add offsets
__global__ void k_scanC() {
    __shared__ int soff;
    int tid = threadIdx.x;
    if (tid < 32) {
        int v = (tid < 20) ? g_bsum[tid] : 0;
        int x = v;
        #pragma unroll
        for (int off = 1; off < 32; off <<= 1) {
            int n = __shfl_up_sync(0xffffffffu, x, off);
            if (tid >= off) x += n;
        }
        if (tid == (int)blockIdx.x) soff = x - v;   // exclusive prefix
    }
    __syncthreads();
    int i = blockIdx.x * 1024 + tid;
    if (i < NN) g_rowptr[i + 1] += soff;
    if (i == 0) g_rowptr[0] = 0;
}

__global__ void k_scatter(const int* __restrict__ ei) {
    int e = blockIdx.x * 256 + threadIdx.x;
    if (e < EE) {
        int s = edge_src(ei, e);
        int d = edge_dst(ei, e);
        if ((unsigned)s < NN && (unsigned)d < NN) {
            int pos = atomicAdd(&g_cursor[d], 1);
            int idx = g_rowptr[d] + pos;
            if ((unsigned)idx < EE) g_csr[idx] = s;
        }
    }
}

// ----------------------------- pre-transform GEMM ----------------------------
// U[n,o] = sum_k xin[n,k]*Wl[o,k];  V[n,o] = sum_k xin[n,k]*Wr[o,k] + bl[o]
// 2D register tiling: thread = 4 rows x 4 outputs, (U,V) packed as f32x2.
template <int DIN, int DOUT>
__global__ void __launch_bounds__(256) k_pre(const float* __restrict__ xin,
                      const float* __restrict__ Wl, const float* __restrict__ Wr,
                      const float* __restrict__ bl,
                      float* __restrict__ U, float* __restrict__ Vout) {
    const int ODIV = DOUT / 4;         // thread-cols (16 or 8)
    const int RT = 1024 / ODIV;        // rows per block (64 or 128)
    const int KT = 32;
    const int XS = KT + 4;
    __shared__ float sX[RT][XS];
    __shared__ unsigned long long sW[KT][DOUT + 2];   // (wl,wr) packed per (k,o)
    int tid = threadIdx.x;
    int o_t = tid % ODIV, r_t = tid / ODIV;
    int r0 = r_t * 4;
    int n0 = blockIdx.x * RT;

    unsigned long long acc[16];
    #pragma unroll
    for (int c = 0; c < 16; c++) acc[c] = 0ull;

    for (int kt = 0; kt < DIN; kt += KT) {
        for (int id = tid; id < KT * DOUT; id += 256) {
            int k = id % KT, o = id / KT;
            float wl_ = Wl[(size_t)o * DIN + kt + k];
            float wr_ = Wr[(size_t)o * DIN + kt + k];
            *(float2*)&sW[k][o] = make_float2(wl_, wr_);
        }
        for (int id = tid; id < RT * KT; id += 256) {
            int k = id % KT, r = id / KT;
            int gr = n0 + r;
            sX[r][k] = (gr < NN) ? xin[(size_t)gr * DIN + kt + k] : 0.f;
        }
        __syncthreads();
        #pragma unroll
        for (int k = 0; k < KT; k++) {
            unsigned long long w[4];
            #pragma unroll
            for (int j = 0; j < 4; j++) w[j] = sW[k][o_t + j * ODIV];
            #pragma unroll
            for (int i = 0; i < 4; i++) {
                unsigned xu = __float_as_uint(sX[r0 + i][k]);
                unsigned long long x2;
                asm("mov.b64 %0, {%1, %1};" : "=l"(x2) : "r"(xu));
                #pragma unroll
                for (int j = 0; j < 4; j++)
                    asm("fma.rn.f32x2 %0, %1, %2, %0;"
                        : "+l"(acc[i * 4 + j]) : "l"(x2), "l"(w[j]));
            }
        }
        __syncthreads();
    }

    #pragma unroll
    for (int i = 0; i < 4; i++) {
        int row = n0 + r0 + i;
        if (row < NN) {
            #pragma unroll
            for (int j = 0; j < 4; j++) {
                unsigned lo, hi;
                asm("mov.b64 {%0, %1}, %2;" : "=r"(lo), "=r"(hi) : "l"(acc[i * 4 + j]));
                int o = o_t + j * ODIV;
                U[(size_t)row * DOUT + o] = __uint_as_float(lo);
                Vout[(size_t)row * DOUT + o] = __uint_as_float(hi) + __ldg(&bl[o]);
            }
        }
    }
}

// ----------------------------- mean-agg + add root term ----------------------
// out[n,:] = mean_{s in N(n)} U[s,:] + V[n,:]
// warp per node; float4 lanes, G neighbor groups per warp, 4-deep unroll.
template <int D>
__global__ void k_aggadd(const float* __restrict__ U, const float* __restrict__ V,
                         float* __restrict__ out) {
    const int LPR = D / 4;     // lanes per row (16 or 8)
    const int G = 32 / LPR;    // neighbor groups (2 or 4)
    int node = blockIdx.x * 8 + (threadIdx.x >> 5);
    int lane = threadIdx.x & 31;
    if (node >= NN) return;
    int sub = lane % LPR, grp = lane / LPR;
    int a = g_rowptr[node], b = g_rowptr[node + 1];
    int deg = b - a;
    float inv = 1.0f / (float)(deg > 0 ? deg : 1);
    const float4* Uv = (const float4*)U;

    float4 s0 = make_float4(0.f, 0.f, 0.f, 0.f), s1 = s0, s2 = s0, s3 = s0;
    int t = a + grp;
    for (; t + 3 * G < b; t += 4 * G) {
        int m0 = g_csr[t], m1 = g_csr[t + G], m2 = g_csr[t + 2 * G], m3 = g_csr[t + 3 * G];
        float4 v0 = __ldg(&Uv[(size_t)m0 * LPR + sub]);
        float4 v1 = __ldg(&Uv[(size_t)m1 * LPR + sub]);
        float4 v2 = __ldg(&Uv[(size_t)m2 * LPR + sub]);
        float4 v3 = __ldg(&Uv[(size_t)m3 * LPR + sub]);
        s0.x += v0.x; s0.y += v0.y; s0.z += v0.z; s0.w += v0.w;
        s1.x += v1.x; s1.y += v1.y; s1.z += v1.z; s1.w += v1.w;
        s2.x += v2.x; s2.y += v2.y; s2.z += v2.z; s2.w += v2.w;
        s3.x += v3.x; s3.y += v3.y; s3.z += v3.z; s3.w += v3.w;
    }
    for (; t < b; t += G) {
        int m0 = g_csr[t];
        float4 v0 = __ldg(&Uv[(size_t)m0 * LPR + sub]);
        s0.x += v0.x; s0.y += v0.y; s0.z += v0.z; s0.w += v0.w;
    }
    float4 acc;
    acc.x = s0.x + s1.x + s2.x + s3.x;
    acc.y = s0.y + s1.y + s2.y + s3.y;
    acc.z = s0.z + s1.z + s2.z + s3.z;
    acc.w = s0.w + s1.w + s2.w + s3.w;
    #pragma unroll
    for (int off = LPR; off < 32; off <<= 1) {
        acc.x += __shfl_xor_sync(0xffffffffu, acc.x, off);
        acc.y += __shfl_xor_sync(0xffffffffu, acc.y, off);
        acc.z += __shfl_xor_sync(0xffffffffu, acc.z, off);
        acc.w += __shfl_xor_sync(0xffffffffu, acc.w, off);
    }
    if (grp == 0) {
        float4 vv = __ldg(&((const float4*)V)[(size_t)node * LPR + sub]);
        float4 res;
        res.x = acc.x * inv + vv.x;
        res.y = acc.y * inv + vv.y;
        res.z = acc.z * inv + vv.z;
        res.w = acc.w * inv + vv.w;
        ((float4*)out)[(size_t)node * LPR + sub] = res;
    }
}

// ----------------------------- conv composition precompute -------------------
__global__ void k_T(const float* __restrict__ Wc1, const float* __restrict__ Wc2,
                    const float* __restrict__ bc1) {
    int m = threadIdx.x;
    int d1 = blockIdx.x / 9, d0 = blockIdx.x % 9;
    float s = 0.f;
    for (int c = 0; c < 64; c++)
        s += Wc2[(m * 64 + c) * 9 + d1] * Wc1[c * 9 + d0];
    g_T[(d1 * 9 + d0) * 64 + m] = s;
    if (d0 == 0) {
        float sb = 0.f;
        for (int c = 0; c < 64; c++)
            sb += Wc2[(m * 64 + c) * 9 + d1] * bc1[c];
        g_Tb[d1 * 64 + m] = sb;
    }
}

__device__ __forceinline__ bool m1(int rc, int d) {
    if (rc == 0) return d >= 0;
    if (rc == 4) return d <= 0;
    return true;
}
__device__ __forceinline__ bool m2(int rc, int s) {
    if (rc == 0) return s >= 0;
    if (rc == 1) return s >= -1;
    if (rc == 3) return s <= 1;
    if (rc == 4) return s <= 0;
    return true;
}

__global__ void k_G(const float* __restrict__ Wc3, const float* __restrict__ bc2,
                    const float* __restrict__ bc3) {
    int cs = blockIdx.x;
    int rc = cs / 5, cc = cs % 5;
    int t = threadIdx.x;
    if (t < 49) {
        int Dr = t / 7 - 3, Dc = t % 7 - 3;
        float acc = 0.f;
        for (int d2 = 0; d2 < 9; d2++) {
            int d2r = d2 / 3 - 1, d2c = d2 % 3 - 1;
            if (!m1(rc, d2r) || !m1(cc, d2c)) continue;
            for (int d1 = 0; d1 < 9; d1++) {
                int d1r = d1 / 3 - 1, d1c = d1 % 3 - 1;
                if (!m2(rc, d2r + d1r) || !m2(cc, d2c + d1c)) continue;
                int d0r = Dr - d2r - d1r, d0c = Dc - d2c - d1c;
                if (d0r < -1 || d0r > 1 || d0c < -1 || d0c > 1) continue;
                int d0 = (d0r + 1) * 3 + (d0c + 1);
                float s = 0.f;
                for (int m = 0; m < 64; m++)
                    s += Wc3[m * 9 + d2] * g_T[(d1 * 9 + d0) * 64 + m];
                acc += s;
            }
        }
        g_G[cs * 49 + t] = acc;
    }
    if (t == 49) {
        float acc = __ldg(&bc3[0]);
        for (int d2 = 0; d2 < 9; d2++) {
            int d2r = d2 / 3 - 1, d2c = d2 % 3 - 1;
            if (!m1(rc, d2r) || !m1(cc, d2c)) continue;
            for (int m = 0; m < 64; m++) acc += Wc3[m * 9 + d2] * bc2[m];
            for (int d1 = 0; d1 < 9; d1++) {
                int d1r = d1 / 3 - 1, d1c = d1 % 3 - 1;
                if (!m2(rc, d2r + d1r) || !m2(cc, d2c + d1c)) continue;
                for (int m = 0; m < 64; m++) acc += Wc3[m * 9 + d2] * g_Tb[d1 * 64 + m];
            }
        }
        g_Bias[cs] = acc;
    }
}

// ---------------- fused (composed-conv + residual + W2 linear) ---------------
__global__ void k_conv(const float* __restrict__ W2, const float* __restrict__ b2) {
    __shared__ float sH[38][64];
    __shared__ float sG[25][49];
    __shared__ float sBias[25];
    __shared__ float sPre[64][33];
    __shared__ float sW[32][65];
    const float* h = g_A;
    float* out = g_B;
    int tid = threadIdx.x;
    int n0 = blockIdx.x * 32;

    for (int id = tid; id < 38 * 64; id += 256) {
        int r = id >> 6, c = id & 63;
        int gr = n0 - 3 + r;
        sH[r][c] = (gr >= 0 && gr < NN) ? h[(size_t)gr * 64 + c] : 0.f;
    }
    for (int id = tid; id < 25 * 49; id += 256) sG[id / 49][id % 49] = g_G[id];
    if (tid < 25) sBias[tid] = g_Bias[tid];
    __syncthreads();

    for (int id = tid; id < 32 * 64; id += 256) {
        int r = id >> 6, c = id & 63;
        int gi = n0 + r;
        int rc = (gi == 0) ? 0 : (gi == 1) ? 1 : (gi == NN - 2) ? 3 : (gi == NN - 1) ? 4 : 2;
        int cc = (c == 0) ? 0 : (c == 1) ? 1 : (c == 62) ? 3 : (c == 63) ? 4 : 2;
        const float* g = sG[rc * 5 + cc];
        float acc = sBias[rc * 5 + cc];
        #pragma unroll
        for (int dr = 0; dr < 7; dr++) {
            #pragma unroll
            for (int dc = 0; dc < 7; dc++) {
                int cj = c + dc - 3;
                if (cj >= 0 && cj < 64)
                    acc += g[dr * 7 + dc] * sH[r + dr][cj];
            }
        }
        acc += sH[r + 3][c];
        sPre[c][r] = acc;
    }
    __syncthreads();

    int o = tid % 64, rg = tid / 64;
    float acc[8];
    #pragma unroll
    for (int r = 0; r < 8; r++) acc[r] = 0.f;
    for (int kt = 0; kt < 64; kt += 32) {
        for (int id = tid; id < 32 * 64; id += 256) {
            int kk = id & 31, oo = id >> 5;
            sW[kk][oo] = W2[oo * 64 + kt + kk];
        }
        __syncthreads();
        #pragma unroll
        for (int k = 0; k < 32; k++) {
            float w = sW[k][o];
            #pragma unroll
            for (int r = 0; r < 8; r++)
                acc[r] += sPre[kt + k][rg * 8 + r] * w;
        }
        __syncthreads();
    }
    float bb = __ldg(&b2[o]);
    #pragma unroll
    for (int r = 0; r < 8; r++)
        out[(size_t)(n0 + rg * 8 + r) * 64 + o] = acc[r] + bb;
}

// ----------------------------- launch ----------------------------------------
extern "C" void kernel_launch(void* const* d_in, const int* in_sizes, int n_in,
                              void* d_out, int out_size) {
    const float* x   = (const float*)d_in[0];
    const int*   ei  = (const int*)d_in[1];
    const float* Wl1 = (const float*)d_in[2];
    const float* bl1 = (const float*)d_in[3];
    const float* Wr1 = (const float*)d_in[4];
    const float* Wl2 = (const float*)d_in[5];
    const float* bl2 = (const float*)d_in[6];
    const float* Wr2 = (const float*)d_in[7];
    const float* Wl3 = (const float*)d_in[8];
    const float* bl3 = (const float*)d_in[9];
    const float* Wr3 = (const float*)d_in[10];
    const float* Wc1 = (const float*)d_in[11];
    const float* bc1 = (const float*)d_in[12];
    const float* Wc2 = (const float*)d_in[13];
    const float* bc2 = (const float*)d_in[14];
    const float* Wc3 = (const float*)d_in[15];
    const float* bc3 = (const float*)d_in[16];
    const float* W2  = (const float*)d_in[17];
    const float* b2  = (const float*)d_in[18];
    float* out = (float*)d_out;

    float *pA, *pB, *pU, *pV;
    cudaGetSymbolAddress((void**)&pA, g_A);
    cudaGetSymbolAddress((void**)&pB, g_B);
    cudaGetSymbolAddress((void**)&pU, g_U);
    cudaGetSymbolAddress((void**)&pV, g_V);

    // init + CSR build
    k_zero<<<(NN + 255) / 256, 256>>>(ei);
    k_hist<<<(EE + 255) / 256, 256>>>(ei);
    k_scanA<<<20, 1024>>>();
    k_scanC<<<20, 1024>>>();
    k_scatter<<<(EE + 255) / 256, 256>>>(ei);

    // conv composition precompute
    k_T<<<81, 64>>>(Wc1, Wc2, bc1);
    k_G<<<25, 64>>>(Wc3, bc2, bc3);

    // sage1: x -> h1 (g_A)
    k_pre<128, 64><<<313, 256>>>(x, Wl1, Wr1, bl1, pU, pV);
    k_aggadd<64><<<2500, 256>>>(pU, pV, pA);
    // sage2: h1 -> h2 (g_A)
    k_pre<64, 64><<<313, 256>>>(pA, Wl2, Wr2, bl2, pU, pV);
    k_aggadd<64><<<2500, 256>>>(pU, pV, pA);
    // sage2 again: h2 -> h3 (g_A)  (= out_1)
    k_pre<64, 64><<<313, 256>>>(pA, Wl2, Wr2, bl2, pU, pV);
    k_aggadd<64><<<2500, 256>>>(pU, pV, pA);

    // composed conv + residual + W2 linear: g_A -> g_B
    k_conv<<<625, 256>>>(W2, b2);

    // sage2: g_B -> g_A
    k_pre<64, 64><<<313, 256>>>(pB, Wl2, Wr2, bl2, pU, pV);
    k_aggadd<64><<<2500, 256>>>(pU, pV, pA);
    // sage2: g_A -> g_B
    k_pre<64, 64><<<313, 256>>>(pA, Wl2, Wr2, bl2, pU, pV);
    k_aggadd<64><<<2500, 256>>>(pU, pV, pB);
    // sage3: g_B -> out (64 -> 32; agg on 32-dim U)
    k_pre<64, 32><<<157, 256>>>(pB, Wl3, Wr3, bl3, pU, pV);
    k_aggadd<32><<<2500, 256>>>(pU, pV, out);
}

// round 6
// speedup vs baseline: 1.1450x; 1.0003x over previous
#include <cuda_runtime.h>
#include <cuda_bf16.h>

#define NN 20000
#define EE 640000

// ----------------------------- device scratch -------------------------------
__device__ __align__(16) float g_A[NN * 64];
__device__ __align__(16) float g_B[NN * 64];
__device__ __align__(16) float g_U[NN * 64];
__device__ __align__(16) float g_V[NN * 64];
__device__ int g_deg[NN];
__device__ int g_cursor[NN];
__device__ int g_rowptr[NN + 1];
__device__ int g_csr[EE];
__device__ int g_bsum[32];
__device__ int g_is64;
__device__ float g_T[81 * 64];
__device__ float g_Tb[9 * 64];
__device__ float g_G[25 * 49];
__device__ float g_Bias[25];

// edge fetch helpers (dtype-agnostic: int32 or int64 edge_index)
__device__ __forceinline__ int edge_src(const int* w, int e) {
    if (g_is64) return (int)((const long long*)w)[e];
    return w[e];
}
__device__ __forceinline__ int edge_dst(const int* w, int e) {
    if (g_is64) return (int)((const long long*)w)[EE + e];
    return w[EE + e];
}

// ----------------------------- GEMM core (shared) ----------------------------
// computes U/V = X @ {Wl,Wr}^T (+bl) for RT rows resident in smem sX.
// thread layout: o_t = tid % (DOUT/4), r_t = tid / (DOUT/4); RPT rows/thread.
template <int DIN, int DOUT, int RT, int XS>
__device__ __forceinline__ void gemm_from_smem(
    const float (*sX)[XS], unsigned long long (*sW)[DOUT + 2],
    const float* __restrict__ Wl, const float* __restrict__ Wr,
    const float* __restrict__ bl,
    float* __restrict__ U, float* __restrict__ Vout, int n0, int tid) {
    const int ODIV = DOUT / 4;
    const int RPT = RT * ODIV / 256;   // rows per thread
    const int KT = 32;
    int o_t = tid % ODIV, r_t = tid / ODIV;
    int r0 = r_t * RPT;

    unsigned long long acc[RPT * 4];
    #pragma unroll
    for (int c = 0; c < RPT * 4; c++) acc[c] = 0ull;

    for (int kt = 0; kt < DIN; kt += KT) {
        for (int id = tid; id < KT * DOUT; id += 256) {
            int k = id % KT, o = id / KT;
            float wl_ = Wl[(size_t)o * DIN + kt + k];
            float wr_ = Wr[(size_t)o * DIN + kt + k];
            *(float2*)&sW[k][o] = make_float2(wl_, wr_);
        }
        __syncthreads();
        #pragma unroll
        for (int k = 0; k < KT; k++) {
            unsigned long long w[4];
            #pragma unroll
            for (int j = 0; j < 4; j++) w[j] = sW[k][o_t + j * ODIV];
            #pragma unroll
            for (int i = 0; i < RPT; i++) {
                unsigned xu = __float_as_uint(sX[r0 + i][kt + k]);
                unsigned long long x2;
                asm("mov.b64 %0, {%1, %1};" : "=l"(x2) : "r"(xu));
                #pragma unroll
                for (int j = 0; j < 4; j++)
                    asm("fma.rn.f32x2 %0, %1, %2, %0;"
                        : "+l"(acc[i * 4 + j]) : "l"(x2), "l"(w[j]));
            }
        }
        __syncthreads();
    }

    #pragma unroll
    for (int i = 0; i < RPT; i++) {
        int row = n0 + r0 + i;
        if (row < NN) {
            #pragma unroll
            for (int j = 0; j < 4; j++) {
                unsigned lo, hi;
                asm("mov.b64 {%0, %1}, %2;" : "=r"(lo), "=r"(hi) : "l"(acc[i * 4 + j]));
                int o = o_t + j * ODIV;
                U[(size_t)row * DOUT + o] = __uint_as_float(lo);
                Vout[(size_t)row * DOUT + o] = __uint_as_float(hi) + __ldg(&bl[o]);
            }
        }
    }
}

// ----------------------------- pre GEMM (+fused deg zero) --------------------
// blocks [0, GB): GEMM; blocks [GB, GB+79): zero deg/cursor (+dtype detect)
template <int DIN, int DOUT, int ZERO>
__global__ void __launch_bounds__(256) k_pre(const float* __restrict__ xin,
                      const float* __restrict__ Wl, const float* __restrict__ Wr,
                      const float* __restrict__ bl,
                      float* __restrict__ U, float* __restrict__ Vout,
                      const int* __restrict__ w, int GB) {
    int tid = threadIdx.x;
    if (ZERO && (int)blockIdx.x >= GB) {
        int i = ((int)blockIdx.x - GB) * 256 + tid;
        if (i < NN) { g_deg[i] = 0; g_cursor[i] = 0; }
        if (i == 0) {
            int all0 = 1;
            for (int j = 0; j < 64; j++)
                if (w[2 * j + 1] != 0) { all0 = 0; break; }
            g_is64 = all0;
        }
        return;
    }
    const int RT = 64;
    const int XS = DIN + 4;
    __shared__ float sX[RT][XS];
    __shared__ unsigned long long sW[32][DOUT + 2];
    int n0 = blockIdx.x * RT;
    for (int id = tid; id < RT * DIN; id += 256) {
        int k = id % DIN, r = id / DIN;
        int gr = n0 + r;
        sX[r][k] = (gr < NN) ? xin[(size_t)gr * DIN + k] : 0.f;
    }
    __syncthreads();
    gemm_from_smem<DIN, DOUT, RT, XS>(sX, sW, Wl, Wr, bl, U, Vout, n0, tid);
}

// ----------------------------- fused agg + GEMM ------------------------------
// h[n,:] = mean_{s in N(n)} Uin[s,:] + Vin[n,:]  (into smem)
// then Uout/Vout = h @ {Wl,Wr}^T (+bl)
template <int DOUT>
__global__ void __launch_bounds__(256) k_aggpre(
    const float* __restrict__ Uin, const float* __restrict__ Vin,
    const float* __restrict__ Wl, const float* __restrict__ Wr,
    const float* __restrict__ bl,
    float* __restrict__ Uout, float* __restrict__ Vout) {
    const int RT = 64, XS = 68;
    __shared__ float sX[RT][XS];
    __shared__ unsigned long long sW[32][DOUT + 2];
    int tid = threadIdx.x;
    int lane = tid & 31, wrp = tid >> 5;
    int n0 = blockIdx.x * RT;
    const float4* Uv = (const float4*)Uin;
    int sub = lane & 15, grp = lane >> 4;   // LPR=16, G=2

    // gather phase: each warp handles 8 node-rows
    for (int i = 0; i < 8; i++) {
        int r = wrp * 8 + i;
        int node = n0 + r;
        if (node >= NN) {
            if (grp == 0) *(float4*)&sX[r][sub * 4] = make_float4(0.f, 0.f, 0.f, 0.f);
            continue;
        }
        int a = g_rowptr[node], b = g_rowptr[node + 1];
        int deg = b - a;
        float inv = 1.0f / (float)(deg > 0 ? deg : 1);
        float4 s0 = make_float4(0.f, 0.f, 0.f, 0.f), s1 = s0, s2 = s0, s3 = s0;
        int t = a + grp;
        for (; t + 6 < b; t += 8) {
            int m0 = g_csr[t], m1 = g_csr[t + 2], m2 = g_csr[t + 4], m3 = g_csr[t + 6];
            float4 v0 = __ldg(&Uv[(size_t)m0 * 16 + sub]);
            float4 v1 = __ldg(&Uv[(size_t)m1 * 16 + sub]);
            float4 v2 = __ldg(&Uv[(size_t)m2 * 16 + sub]);
            float4 v3 = __ldg(&Uv[(size_t)m3 * 16 + sub]);
            s0.x += v0.x; s0.y += v0.y; s0.z += v0.z; s0.w += v0.w;
            s1.x += v1.x; s1.y += v1.y; s1.z += v1.z; s1.w += v1.w;
            s2.x += v2.x; s2.y += v2.y; s2.z += v2.z; s2.w += v2.w;
            s3.x += v3.x; s3.y += v3.y; s3.z += v3.z; s3.w += v3.w;
        }
        for (; t < b; t += 2) {
            float4 v0 = __ldg(&Uv[(size_t)g_csr[t] * 16 + sub]);
            s0.x += v0.x; s0.y += v0.y; s0.z += v0.z; s0.w += v0.w;
        }
        float4 acc;
        acc.x = s0.x + s1.x + s2.x + s3.x;
        acc.y = s0.y + s1.y + s2.y + s3.y;
        acc.z = s0.z + s1.z + s2.z + s3.z;
        acc.w = s0.w + s1.w + s2.w + s3.w;
        acc.x += __shfl_xor_sync(0xffffffffu, acc.x, 16);
        acc.y += __shfl_xor_sync(0xffffffffu, acc.y, 16);
        acc.z += __shfl_xor_sync(0xffffffffu, acc.z, 16);
        acc.w += __shfl_xor_sync(0xffffffffu, acc.w, 16);
        if (grp == 0) {
            float4 vv = __ldg(&((const float4*)Vin)[(size_t)node * 16 + sub]);
            *(float4*)&sX[r][sub * 4] = make_float4(
                acc.x * inv + vv.x, acc.y * inv + vv.y,
                acc.z * inv + vv.z, acc.w * inv + vv.w);
        }
    }
    __syncthreads();
    gemm_from_smem<64, DOUT, RT, XS>(sX, sW, Wl, Wr, bl, Uout, Vout, n0, tid);
}

// ----------------------------- CSR build ------------------------------------
__global__ void k_hist(const int* __restrict__ ei) {
    int e = blockIdx.x * 256 + threadIdx.x;
    if (e < EE) {
        int d = edge_dst(ei, e);
        if ((unsigned)d < NN) atomicAdd(&g_deg[d], 1);
    }
}

__global__ void k_scanA() {
    __shared__ int ws[32];
    int tid = threadIdx.x, lane = tid & 31, wid = tid >> 5;
    int i = blockIdx.x * 1024 + tid;
    int v = (i < NN) ? g_deg[i] : 0;
    int x = v;
    #pragma unroll
    for (int off = 1; off < 32; off <<= 1) {
        int n = __shfl_up_sync(0xffffffffu, x, off);
        if (lane >= off) x += n;
    }
    if (lane == 31) ws[wid] = x;
    __syncthreads();
    if (wid == 0) {
        int w = ws[lane];
        #pragma unroll
        for (int off = 1; off < 32; off <<= 1) {
            int n = __shfl_up_sync(0xffffffffu, w, off);
            if (lane >= off) w += n;
        }
        ws[lane] = w;
    }
    __syncthreads();
    int incl = x + (wid ? ws[wid - 1] : 0);
    if (i < NN) g_rowptr[i + 1] = incl;
    if (tid == 1023) g_bsum[blockIdx.x] = incl;
}

__global__ void k_scanC() {
    __shared__ int soff;
    int tid = threadIdx.x;
    if (tid < 32) {
        int v = (tid < 20) ? g_bsum[tid] : 0;
        int x = v;
        #pragma unroll
        for (int off = 1; off < 32; off <<= 1) {
            int n = __shfl_up_sync(0xffffffffu, x, off);
            if (tid >= off) x += n;
        }
        if (tid == (int)blockIdx.x) soff = x - v;
    }
    __syncthreads();
    int i = blockIdx.x * 1024 + tid;
    if (i < NN) g_rowptr[i + 1] += soff;
    if (i == 0) g_rowptr[0] = 0;
}

__global__ void k_scatter(const int* __restrict__ ei) {
    int e = blockIdx.x * 256 + threadIdx.x;
    if (e < EE) {
        int s = edge_src(ei, e);
        int d = edge_dst(ei, e);
        if ((unsigned)s < NN && (unsigned)d < NN) {
            int pos = atomicAdd(&g_cursor[d], 1);
            int idx = g_rowptr[d] + pos;
            if ((unsigned)idx < EE) g_csr[idx] = s;
        }
    }
}

// ----------------------------- plain agg + add -------------------------------
template <int D>
__global__ void k_aggadd(const float* __restrict__ U, const float* __restrict__ V,
                         float* __restrict__ out) {
    const int LPR = D / 4;
    const int G = 32 / LPR;
    int node = blockIdx.x * 8 + (threadIdx.x >> 5);
    int lane = threadIdx.x & 31;
    if (node >= NN) return;
    int sub = lane % LPR, grp = lane / LPR;
    int a = g_rowptr[node], b = g_rowptr[node + 1];
    int deg = b - a;
    float inv = 1.0f / (float)(deg > 0 ? deg : 1);
    const float4* Uv = (const float4*)U;

    float4 s0 = make_float4(0.f, 0.f, 0.f, 0.f), s1 = s0, s2 = s0, s3 = s0;
    int t = a + grp;
    for (; t + 3 * G < b; t += 4 * G) {
        int m0 = g_csr[t], m1 = g_csr[t + G], m2 = g_csr[t + 2 * G], m3 = g_csr[t + 3 * G];
        float4 v0 = __ldg(&Uv[(size_t)m0 * LPR + sub]);
        float4 v1 = __ldg(&Uv[(size_t)m1 * LPR + sub]);
        float4 v2 = __ldg(&Uv[(size_t)m2 * LPR + sub]);
        float4 v3 = __ldg(&Uv[(size_t)m3 * LPR + sub]);
        s0.x += v0.x; s0.y += v0.y; s0.z += v0.z; s0.w += v0.w;
        s1.x += v1.x; s1.y += v1.y; s1.z += v1.z; s1.w += v1.w;
        s2.x += v2.x; s2.y += v2.y; s2.z += v2.z; s2.w += v2.w;
        s3.x += v3.x; s3.y += v3.y; s3.z += v3.z; s3.w += v3.w;
    }
    for (; t < b; t += G) {
        float4 v0 = __ldg(&Uv[(size_t)g_csr[t] * LPR + sub]);
        s0.x += v0.x; s0.y += v0.y; s0.z += v0.z; s0.w += v0.w;
    }
    float4 acc;
    acc.x = s0.x + s1.x + s2.x + s3.x;
    acc.y = s0.y + s1.y + s2.y + s3.y;
    acc.z = s0.z + s1.z + s2.z + s3.z;
    acc.w = s0.w + s1.w + s2.w + s3.w;
    #pragma unroll
    for (int off = LPR; off < 32; off <<= 1) {
        acc.x += __shfl_xor_sync(0xffffffffu, acc.x, off);
        acc.y += __shfl_xor_sync(0xffffffffu, acc.y, off);
        acc.z += __shfl_xor_sync(0xffffffffu, acc.z, off);
        acc.w += __shfl_xor_sync(0xffffffffu, acc.w, off);
    }
    if (grp == 0) {
        float4 vv = __ldg(&((const float4*)V)[(size_t)node * LPR + sub]);
        float4 res;
        res.x = acc.x * inv + vv.x;
        res.y = acc.y * inv + vv.y;
        res.z = acc.z * inv + vv.z;
        res.w = acc.w * inv + vv.w;
        ((float4*)out)[(size_t)node * LPR + sub] = res;
    }
}

// ----------------------------- conv composition precompute -------------------
__global__ void k_T(const float* __restrict__ Wc1, const float* __restrict__ Wc2,
                    const float* __restrict__ bc1) {
    int m = threadIdx.x;
    int d1 = blockIdx.x / 9, d0 = blockIdx.x % 9;
    float s = 0.f;
    for (int c = 0; c < 64; c++)
        s += Wc2[(m * 64 + c) * 9 + d1] * Wc1[c * 9 + d0];
    g_T[(d1 * 9 + d0) * 64 + m] = s;
    if (d0 == 0) {
        float sb = 0.f;
        for (int c = 0; c < 64; c++)
            sb += Wc2[(m * 64 + c) * 9 + d1] * bc1[c];
        g_Tb[d1 * 64 + m] = sb;
    }
}

__device__ __forceinline__ bool m1(int rc, int d) {
    if (rc == 0) return d >= 0;
    if (rc == 4) return d <= 0;
    return true;
}
__device__ __forceinline__ bool m2(int rc, int s) {
    if (rc == 0) return s >= 0;
    if (rc == 1) return s >= -1;
    if (rc == 3) return s <= 1;
    if (rc == 4) return s <= 0;
    return true;
}

__global__ void k_G(const float* __restrict__ Wc3, const float* __restrict__ bc2,
                    const float* __restrict__ bc3) {
    int cs = blockIdx.x;
    int rc = cs / 5, cc = cs % 5;
    int t = threadIdx.x;
    if (t < 49) {
        int Dr = t / 7 - 3, Dc = t % 7 - 3;
        float acc = 0.f;
        for (int d2 = 0; d2 < 9; d2++) {
            int d2r = d2 / 3 - 1, d2c = d2 % 3 - 1;
            if (!m1(rc, d2r) || !m1(cc, d2c)) continue;
            for (int d1 = 0; d1 < 9; d1++) {
                int d1r = d1 / 3 - 1, d1c = d1 % 3 - 1;
                if (!m2(rc, d2r + d1r) || !m2(cc, d2c + d1c)) continue;
                int d0r = Dr - d2r - d1r, d0c = Dc - d2c - d1c;
                if (d0r < -1 || d0r > 1 || d0c < -1 || d0c > 1) continue;
                int d0 = (d0r + 1) * 3 + (d0c + 1);
                float s = 0.f;
                for (int m = 0; m < 64; m++)
                    s += Wc3[m * 9 + d2] * g_T[(d1 * 9 + d0) * 64 + m];
                acc += s;
            }
        }
        g_G[cs * 49 + t] = acc;
    }
    if (t == 49) {
        float acc = __ldg(&bc3[0]);
        for (int d2 = 0; d2 < 9; d2++) {
            int d2r = d2 / 3 - 1, d2c = d2 % 3 - 1;
            if (!m1(rc, d2r) || !m1(cc, d2c)) continue;
            for (int m = 0; m < 64; m++) acc += Wc3[m * 9 + d2] * bc2[m];
            for (int d1 = 0; d1 < 9; d1++) {
                int d1r = d1 / 3 - 1, d1c = d1 % 3 - 1;
                if (!m2(rc, d2r + d1r) || !m2(cc, d2c + d1c)) continue;
                for (int m = 0; m < 64; m++) acc += Wc3[m * 9 + d2] * g_Tb[d1 * 64 + m];
            }
        }
        g_Bias[cs] = acc;
    }
}

// ---------------- fused (composed-conv + residual + W2 linear) ---------------
__global__ void k_conv(const float* __restrict__ hin, float* __restrict__ out,
                       const float* __restrict__ W2, const float* __restrict__ b2) {
    __shared__ float sH[38][64];
    __shared__ float sG[25][49];
    __shared__ float sBias[25];
    __shared__ float sPre[64][33];
    __shared__ float sW[32][65];
    int tid = threadIdx.x;
    int n0 = blockIdx.x * 32;

    for (int id = tid; id < 38 * 64; id += 256) {
        int r = id >> 6, c = id & 63;
        int gr = n0 - 3 + r;
        sH[r][c] = (gr >= 0 && gr < NN) ? hin[(size_t)gr * 64 + c] : 0.f;
    }
    for (int id = tid; id < 25 * 49; id += 256) sG[id / 49][id % 49] = g_G[id];
    if (tid < 25) sBias[tid] = g_Bias[tid];
    __syncthreads();

    for (int id = tid; id < 32 * 64; id += 256) {
        int r = id >> 6, c = id & 63;
        int gi = n0 + r;
        int rc = (gi == 0) ? 0 : (gi == 1) ? 1 : (gi == NN - 2) ? 3 : (gi == NN - 1) ? 4 : 2;
        int cc = (c == 0) ? 0 : (c == 1) ? 1 : (c == 62) ? 3 : (c == 63) ? 4 : 2;
        const float* g = sG[rc * 5 + cc];
        float acc = sBias[rc * 5 + cc];
        #pragma unroll
        for (int dr = 0; dr < 7; dr++) {
            #pragma unroll
            for (int dc = 0; dc < 7; dc++) {
                int cj = c + dc - 3;
                if (cj >= 0 && cj < 64)
                    acc += g[dr * 7 + dc] * sH[r + dr][cj];
            }
        }
        acc += sH[r + 3][c];
        sPre[c][r] = acc;
    }
    __syncthreads();

    int o = tid % 64, rg = tid / 64;
    float acc[8];
    #pragma unroll
    for (int r = 0; r < 8; r++) acc[r] = 0.f;
    for (int kt = 0; kt < 64; kt += 32) {
        for (int id = tid; id < 32 * 64; id += 256) {
            int kk = id & 31, oo = id >> 5;
            sW[kk][oo] = W2[oo * 64 + kt + kk];
        }
        __syncthreads();
        #pragma unroll
        for (int k = 0; k < 32; k++) {
            float w = sW[k][o];
            #pragma unroll
            for (int r = 0; r < 8; r++)
                acc[r] += sPre[kt + k][rg * 8 + r] * w;
        }
        __syncthreads();
    }
    float bb = __ldg(&b2[o]);
    #pragma unroll
    for (int r = 0; r < 8; r++)
        out[(size_t)(n0 + rg * 8 + r) * 64 + o] = acc[r] + bb;
}

// ----------------------------- launch ----------------------------------------
extern "C" void kernel_launch(void* const* d_in, const int* in_sizes, int n_in,
                              void* d_out, int out_size) {
    const float* x   = (const float*)d_in[0];
    const int*   ei  = (const int*)d_in[1];
    const float* Wl1 = (const float*)d_in[2];
    const float* bl1 = (const float*)d_in[3];
    const float* Wr1 = (const float*)d_in[4];
    const float* Wl2 = (const float*)d_in[5];
    const float* bl2 = (const float*)d_in[6];
    const float* Wr2 = (const float*)d_in[7];
    const float* Wl3 = (const float*)d_in[8];
    const float* bl3 = (const float*)d_in[9];
    const float* Wr3 = (const float*)d_in[10];
    const float* Wc1 = (const float*)d_in[11];
    const float* bc1 = (const float*)d_in[12];
    const float* Wc2 = (const float*)d_in[13];
    const float* bc2 = (const float*)d_in[14];
    const float* Wc3 = (const float*)d_in[15];
    const float* bc3 = (const float*)d_in[16];
    const float* W2  = (const float*)d_in[17];
    const float* b2  = (const float*)d_in[18];
    float* out = (float*)d_out;

    float *pA, *pB, *pU, *pV;
    cudaGetSymbolAddress((void**)&pA, g_A);
    cudaGetSymbolAddress((void**)&pB, g_B);
    cudaGetSymbolAddress((void**)&pU, g_U);
    cudaGetSymbolAddress((void**)&pV, g_V);

    // 1: pre1 (x -> U,V) fused with deg/cursor zero + dtype detect
    k_pre<128, 64, 1><<<313 + 79, 256>>>(x, Wl1, Wr1, bl1, pU, pV, ei, 313);
    // 2-5: CSR build
    k_hist<<<(EE + 255) / 256, 256>>>(ei);
    k_scanA<<<20, 1024>>>();
    k_scanC<<<20, 1024>>>();
    k_scatter<<<(EE + 255) / 256, 256>>>(ei);

    // 6: sage2 fused (agg(U,V) -> h2, GEMM -> A,B)   [ncu capture slot]
    k_aggpre<64><<<313, 256>>>(pU, pV, Wl2, Wr2, bl2, pA, pB);
    // 7: sage2 fused (A,B) -> (U,V)
    k_aggpre<64><<<313, 256>>>(pA, pB, Wl2, Wr2, bl2, pU, pV);
    // 8: h3 = agg(U,V) -> A   (conv input = out_1)
    k_aggadd<64><<<2500, 256>>>(pU, pV, pA);

    // 9-10: conv composition precompute
    k_T<<<81, 64>>>(Wc1, Wc2, bc1);
    k_G<<<25, 64>>>(Wc3, bc2, bc3);

    // 11: composed conv + residual + W2 linear: A -> B
    k_conv<<<625, 256>>>(pA, pB, W2, b2);

    // 12: pre (B -> U,V)
    k_pre<64, 64, 0><<<313, 256>>>(pB, Wl2, Wr2, bl2, pU, pV, nullptr, 313);
    // 13: sage2 fused (U,V) -> (A,B)
    k_aggpre<64><<<313, 256>>>(pU, pV, Wl2, Wr2, bl2, pA, pB);
    // 14: sage3 fused (A,B) -> (U,V)  (DOUT=32)
    k_aggpre<32><<<313, 256>>>(pA, pB, Wl3, Wr3, bl3, pU, pV);
    // 15: out = agg(U,V) (32-dim)
    k_aggadd<32><<<2500, 256>>>(pU, pV, out);
}